// round 2
// baseline (speedup 1.0000x reference)
#include <cuda_runtime.h>
#include <math.h>

#define BB 4
#define SS 1024
#define DD 1024
#define HH 16
#define HDIM 64
#define MROWS (BB*SS)   /* 4096 */
#define FFD (4*DD)      /* 4096 */
#define LN_EPS 1e-5f
#define F_INF __int_as_float(0x7f800000)

/* ---------------- scratch pool (no cudaMalloc allowed) ---------------- */
/* layout (floats):
   q:0..4M  k:4M..8M  v:8M..12M  ctx:12M..16M  x1:16M..20M  tmp:20M..24M
   h:24M..40M  scores:40M..104M                                            */
#define OFF_Q   (0ul)
#define OFF_K   (4ul<<20)
#define OFF_V   (8ul<<20)
#define OFF_CTX (12ul<<20)
#define OFF_X1  (16ul<<20)
#define OFF_TMP (20ul<<20)
#define OFF_H   (24ul<<20)
#define OFF_SC  (40ul<<20)
#define POOL_FLOATS (104ul<<20)
__device__ __align__(256) float g_pool[POOL_FLOATS];

/* ---------------- reductions ---------------- */
__device__ __forceinline__ float warpSum(float v) {
    #pragma unroll
    for (int o = 16; o; o >>= 1) v += __shfl_xor_sync(0xffffffffu, v, o);
    return v;
}
__device__ __forceinline__ float warpMax(float v) {
    #pragma unroll
    for (int o = 16; o; o >>= 1) v = fmaxf(v, __shfl_xor_sync(0xffffffffu, v, o));
    return v;
}
/* 256-thread block reductions; red must be shared float[8] */
__device__ __forceinline__ float blockSum(float v, float* red) {
    int lane = threadIdx.x & 31, w = threadIdx.x >> 5;
    v = warpSum(v);
    __syncthreads();
    if (lane == 0) red[w] = v;
    __syncthreads();
    float r = (lane < 8) ? red[lane] : 0.f;
    r = warpSum(r);
    return r;
}
__device__ __forceinline__ float blockMax(float v, float* red) {
    int lane = threadIdx.x & 31, w = threadIdx.x >> 5;
    v = warpMax(v);
    __syncthreads();
    if (lane == 0) red[w] = v;
    __syncthreads();
    float r = (lane < 8) ? red[lane] : -F_INF;
    r = warpMax(r);
    return r;
}

/* ---------------- SGEMM: C[M,N] = A[M,K] @ W[K,N] + bias (+relu / +res) ----------------
   EPI: 0 = bias only, 1 = relu(bias), 2 = bias + residual add                           */
#define GBM 128
#define GBN 128
#define GBK 8
template<int EPI>
__global__ void __launch_bounds__(256)
sgemm_kernel(const float* __restrict__ A, const float* __restrict__ W,
             const float* __restrict__ bias, const float* __restrict__ res,
             float* __restrict__ C, int M, int N, int K)
{
    __shared__ float As[GBK][GBM];
    __shared__ float Bs[GBK][GBN];

    const int tid = threadIdx.x;
    const int row0 = blockIdx.y * GBM;
    const int col0 = blockIdx.x * GBN;

    const int arow = tid >> 1;          /* 0..127 */
    const int acol = (tid & 1) * 4;     /* 0 or 4 */
    const int brow = tid >> 5;          /* 0..7   */
    const int bcol = (tid & 31) * 4;    /* 0..124 */

    const int ty = tid >> 4;            /* 0..15 */
    const int tx = tid & 15;            /* 0..15 */

    float acc[8][8];
    #pragma unroll
    for (int i = 0; i < 8; i++)
        #pragma unroll
        for (int j = 0; j < 8; j++) acc[i][j] = 0.f;

    for (int k0 = 0; k0 < K; k0 += GBK) {
        float4 av = *(const float4*)&A[(size_t)(row0 + arow) * K + k0 + acol];
        As[acol + 0][arow] = av.x;
        As[acol + 1][arow] = av.y;
        As[acol + 2][arow] = av.z;
        As[acol + 3][arow] = av.w;
        *(float4*)&Bs[brow][bcol] =
            *(const float4*)&W[(size_t)(k0 + brow) * N + col0 + bcol];
        __syncthreads();

        #pragma unroll
        for (int kk = 0; kk < GBK; kk++) {
            float a[8], b[8];
            float4 a0 = *(float4*)&As[kk][ty * 8];
            float4 a1 = *(float4*)&As[kk][ty * 8 + 4];
            a[0]=a0.x; a[1]=a0.y; a[2]=a0.z; a[3]=a0.w;
            a[4]=a1.x; a[5]=a1.y; a[6]=a1.z; a[7]=a1.w;
            float4 b0 = *(float4*)&Bs[kk][tx * 8];
            float4 b1 = *(float4*)&Bs[kk][tx * 8 + 4];
            b[0]=b0.x; b[1]=b0.y; b[2]=b0.z; b[3]=b0.w;
            b[4]=b1.x; b[5]=b1.y; b[6]=b1.z; b[7]=b1.w;
            #pragma unroll
            for (int i = 0; i < 8; i++)
                #pragma unroll
                for (int j = 0; j < 8; j++)
                    acc[i][j] = fmaf(a[i], b[j], acc[i][j]);
        }
        __syncthreads();
    }

    #pragma unroll
    for (int i = 0; i < 8; i++) {
        const int r = row0 + ty * 8 + i;
        #pragma unroll
        for (int j = 0; j < 8; j++) {
            const int c = col0 + tx * 8 + j;
            float v = acc[i][j] + bias[c];
            if (EPI == 1) v = fmaxf(v, 0.f);
            if (EPI == 2) v += res[(size_t)r * N + c];
            C[(size_t)r * N + c] = v;
        }
    }
}

/* ---------------- attention scores: S[b,h,q,k] = (Q.K^T)/8 masked ---------------- */
__global__ void __launch_bounds__(256)
scores_kernel(const float* __restrict__ Q, const float* __restrict__ Kmat,
              const int* __restrict__ mask, float* __restrict__ sc)
{
    __shared__ float Qs[64][65];
    __shared__ float Ks[64][65];
    const int tid = threadIdx.x;
    const int bh = blockIdx.z;            /* b*H + h */
    const int b = bh >> 4, h = bh & 15;
    const int q0 = blockIdx.y * 64, k0 = blockIdx.x * 64;

    const float* Qb = Q + ((size_t)b * SS + q0) * DD + h * HDIM;
    const float* Kb = Kmat + ((size_t)b * SS + k0) * DD + h * HDIM;

    for (int idx = tid; idx < 64 * 64; idx += 256) {
        int r = idx >> 6, c = idx & 63;
        Qs[r][c] = Qb[(size_t)r * DD + c];
        Ks[r][c] = Kb[(size_t)r * DD + c];
    }
    __syncthreads();

    const int ty = tid >> 4, tx = tid & 15;
    float acc[4][4];
    #pragma unroll
    for (int i = 0; i < 4; i++)
        #pragma unroll
        for (int j = 0; j < 4; j++) acc[i][j] = 0.f;

    #pragma unroll 8
    for (int d = 0; d < 64; d++) {
        float qv[4], kv[4];
        #pragma unroll
        for (int i = 0; i < 4; i++) qv[i] = Qs[ty * 4 + i][d];
        #pragma unroll
        for (int j = 0; j < 4; j++) kv[j] = Ks[tx * 4 + j][d];
        #pragma unroll
        for (int i = 0; i < 4; i++)
            #pragma unroll
            for (int j = 0; j < 4; j++)
                acc[i][j] = fmaf(qv[i], kv[j], acc[i][j]);
    }

    const size_t base = ((size_t)bh * SS + q0) * SS + k0;
    #pragma unroll
    for (int i = 0; i < 4; i++) {
        #pragma unroll
        for (int j = 0; j < 4; j++) {
            size_t off = base + (size_t)(ty * 4 + i) * SS + tx * 4 + j;
            float v = acc[i][j] * 0.125f;
            if (mask[off] != 0) v = -F_INF;
            sc[off] = v;
        }
    }
}

/* ---------------- softmax over last dim, in place ---------------- */
__global__ void __launch_bounds__(256)
softmax_kernel(float* __restrict__ sc)
{
    __shared__ float red[8];
    const size_t base = (size_t)blockIdx.x * SS;
    const int tid = threadIdx.x;
    float v[4];
    #pragma unroll
    for (int i = 0; i < 4; i++) v[i] = sc[base + tid + i * 256];

    float m = fmaxf(fmaxf(v[0], v[1]), fmaxf(v[2], v[3]));
    m = blockMax(m, red);

    float p[4], s = 0.f;
    #pragma unroll
    for (int i = 0; i < 4; i++) { p[i] = __expf(v[i] - m); s += p[i]; }
    s = blockSum(s, red);
    const float inv = 1.f / s;
    #pragma unroll
    for (int i = 0; i < 4; i++) sc[base + tid + i * 256] = p[i] * inv;
}

/* ---------------- ctx[b,q,h,:] = attn[b,h,q,:] @ V[b,:,h,:] ---------------- */
__global__ void __launch_bounds__(256)
ctx_kernel(const float* __restrict__ attn, const float* __restrict__ V,
           float* __restrict__ ctx)
{
    __shared__ float As[64][33];
    __shared__ float Bs[32][65];
    const int tid = threadIdx.x;
    const int bh = blockIdx.y;
    const int b = bh >> 4, h = bh & 15;
    const int q0 = blockIdx.x * 64;

    const float* Arow = attn + ((size_t)bh * SS + q0) * SS;
    const float* Vb = V + (size_t)b * SS * DD + h * HDIM;

    const int ty = tid >> 4, tx = tid & 15;
    float acc[4][4];
    #pragma unroll
    for (int i = 0; i < 4; i++)
        #pragma unroll
        for (int j = 0; j < 4; j++) acc[i][j] = 0.f;

    for (int k0 = 0; k0 < SS; k0 += 32) {
        for (int idx = tid; idx < 64 * 32; idx += 256) {
            int r = idx >> 5, c = idx & 31;
            As[r][c] = Arow[(size_t)r * SS + k0 + c];
        }
        for (int idx = tid; idx < 32 * 64; idx += 256) {
            int r = idx >> 6, c = idx & 63;
            Bs[r][c] = Vb[(size_t)(k0 + r) * DD + c];
        }
        __syncthreads();
        #pragma unroll 8
        for (int kk = 0; kk < 32; kk++) {
            float a[4], bvv[4];
            #pragma unroll
            for (int i = 0; i < 4; i++) a[i] = As[ty * 4 + i][kk];
            #pragma unroll
            for (int j = 0; j < 4; j++) bvv[j] = Bs[kk][tx * 4 + j];
            #pragma unroll
            for (int i = 0; i < 4; i++)
                #pragma unroll
                for (int j = 0; j < 4; j++)
                    acc[i][j] = fmaf(a[i], bvv[j], acc[i][j]);
        }
        __syncthreads();
    }

    #pragma unroll
    for (int i = 0; i < 4; i++)
        #pragma unroll
        for (int j = 0; j < 4; j++)
            ctx[(size_t)b * SS * DD + (size_t)(q0 + ty * 4 + i) * DD
                + h * HDIM + tx * 4 + j] = acc[i][j];
}

/* ---------------- LayerNorm over D (input already has residual added) ---------------- */
__global__ void __launch_bounds__(256)
ln_kernel(const float* __restrict__ in, const float* __restrict__ g,
          const float* __restrict__ beta, float* __restrict__ out)
{
    __shared__ float red[8];
    const size_t base = (size_t)blockIdx.x * DD;
    const int tid = threadIdx.x;
    float v[4];
    #pragma unroll
    for (int i = 0; i < 4; i++) v[i] = in[base + tid + i * 256];

    float s = v[0] + v[1] + v[2] + v[3];
    const float mu = blockSum(s, red) * (1.f / DD);

    float sq = 0.f;
    #pragma unroll
    for (int i = 0; i < 4; i++) { v[i] -= mu; sq += v[i] * v[i]; }
    const float var = blockSum(sq, red) * (1.f / DD);
    const float r = rsqrtf(var + LN_EPS);

    #pragma unroll
    for (int i = 0; i < 4; i++) {
        int c = tid + i * 256;
        out[base + c] = v[i] * r * g[c] + beta[c];
    }
}

/* ---------------- launch ---------------- */
extern "C" void kernel_launch(void* const* d_in, const int* in_sizes, int n_in,
                              void* d_out, int out_size)
{
    const float* x    = (const float*)d_in[0];
    const float* y    = (const float*)d_in[1];
    const int* mask   = (const int*)d_in[2];
    const float* Wq = (const float*)d_in[3];
    const float* bq = (const float*)d_in[4];
    const float* Wk = (const float*)d_in[5];
    const float* bk = (const float*)d_in[6];
    const float* Wv = (const float*)d_in[7];
    const float* bv = (const float*)d_in[8];
    const float* Wo = (const float*)d_in[9];
    const float* bo = (const float*)d_in[10];
    const float* W1 = (const float*)d_in[11];
    const float* b1 = (const float*)d_in[12];
    const float* W2 = (const float*)d_in[13];
    const float* b2 = (const float*)d_in[14];
    const float* g1 = (const float*)d_in[15];
    const float* be1 = (const float*)d_in[16];
    const float* g2 = (const float*)d_in[17];
    const float* be2 = (const float*)d_in[18];
    float* out = (float*)d_out;

    float* pool = nullptr;
    cudaGetSymbolAddress((void**)&pool, g_pool);
    float* q   = pool + OFF_Q;
    float* k   = pool + OFF_K;
    float* v   = pool + OFF_V;
    float* ctx = pool + OFF_CTX;
    float* x1  = pool + OFF_X1;
    float* tmp = pool + OFF_TMP;
    float* h   = pool + OFF_H;
    float* sc  = pool + OFF_SC;

    dim3 gProj(DD / GBN, MROWS / GBM);      /* 8 x 32 */
    dim3 gFF1(FFD / GBN, MROWS / GBM);      /* 32 x 32 */

    /* QKV projections */
    sgemm_kernel<0><<<gProj, 256>>>(x, Wq, bq, nullptr, q, MROWS, DD, DD);
    sgemm_kernel<0><<<gProj, 256>>>(y, Wk, bk, nullptr, k, MROWS, DD, DD);
    sgemm_kernel<0><<<gProj, 256>>>(y, Wv, bv, nullptr, v, MROWS, DD, DD);

    /* attention */
    scores_kernel<<<dim3(SS / 64, SS / 64, BB * HH), 256>>>(q, k, mask, sc);
    softmax_kernel<<<BB * HH * SS, 256>>>(sc);
    ctx_kernel<<<dim3(SS / 64, BB * HH), 256>>>(sc, v, ctx);

    /* output proj + residual, LN1 */
    sgemm_kernel<2><<<gProj, 256>>>(ctx, Wo, bo, x, tmp, MROWS, DD, DD);
    ln_kernel<<<MROWS, 256>>>(tmp, g1, be1, x1);

    /* FFN */
    sgemm_kernel<1><<<gFF1, 256>>>(x1, W1, b1, nullptr, h, MROWS, FFD, DD);
    sgemm_kernel<2><<<gProj, 256>>>(h, W2, b2, x1, tmp, MROWS, DD, FFD);
    ln_kernel<<<MROWS, 256>>>(tmp, g2, be2, out);
}

// round 4
// speedup vs baseline: 2.7327x; 2.7327x over previous
#include <cuda_runtime.h>
#include <math.h>
#include <stdint.h>

#define BB 4
#define SS 1024
#define DD 1024
#define HH 16
#define HDIM 64
#define MROWS (BB*SS)   /* 4096 */
#define FFD (4*DD)      /* 4096 */
#define LN_EPS 1e-5f
#define F_INF __int_as_float(0x7f800000)

/* ---------------- scratch pool ---------------- */
#define OFF_Q   (0ul)
#define OFF_K   (4ul<<20)
#define OFF_V   (8ul<<20)
#define OFF_CTX (12ul<<20)
#define OFF_X1  (16ul<<20)
#define OFF_TMP (20ul<<20)
#define OFF_H   (24ul<<20)
#define OFF_SC  (40ul<<20)
#define POOL_FLOATS (104ul<<20)
__device__ __align__(256) float g_pool[POOL_FLOATS];

/* ---------------- tf32 helpers ---------------- */
__device__ __forceinline__ float to_tf32(float x) {
    uint32_t r;
    asm("cvt.rna.tf32.f32 %0, %1;" : "=r"(r) : "f"(x));
    return __uint_as_float(r);
}
__device__ __forceinline__ void mma_tf32(float c[4],
                                         uint32_t a0, uint32_t a1, uint32_t a2, uint32_t a3,
                                         uint32_t b0, uint32_t b1) {
    asm volatile(
        "mma.sync.aligned.m16n8k8.row.col.f32.tf32.tf32.f32 "
        "{%0,%1,%2,%3}, {%4,%5,%6,%7}, {%8,%9}, {%0,%1,%2,%3};"
        : "+f"(c[0]), "+f"(c[1]), "+f"(c[2]), "+f"(c[3])
        : "r"(a0), "r"(a1), "r"(a2), "r"(a3), "r"(b0), "r"(b1));
}
__device__ __forceinline__ uint32_t fu(float x) { return __float_as_uint(x); }

/* ---------------- reductions ---------------- */
__device__ __forceinline__ float warpSum(float v) {
    #pragma unroll
    for (int o = 16; o; o >>= 1) v += __shfl_xor_sync(0xffffffffu, v, o);
    return v;
}
__device__ __forceinline__ float warpMax(float v) {
    #pragma unroll
    for (int o = 16; o; o >>= 1) v = fmaxf(v, __shfl_xor_sync(0xffffffffu, v, o));
    return v;
}
__device__ __forceinline__ float blockSum(float v, float* red) {
    int lane = threadIdx.x & 31, w = threadIdx.x >> 5;
    v = warpSum(v);
    __syncthreads();
    if (lane == 0) red[w] = v;
    __syncthreads();
    float r = (lane < 8) ? red[lane] : 0.f;
    return warpSum(r);
}
__device__ __forceinline__ float blockMax(float v, float* red) {
    int lane = threadIdx.x & 31, w = threadIdx.x >> 5;
    v = warpMax(v);
    __syncthreads();
    if (lane == 0) red[w] = v;
    __syncthreads();
    float r = (lane < 8) ? red[lane] : -F_INF;
    return warpMax(r);
}

/* =====================================================================
   Dense GEMM via tf32 mma: C[M,N] = A[M,K] @ W[K,N] + bias (+relu/+res)
   CTA 128x128, 256 thr (8 warps, 2x4), warp tile 64x32, K step 32.
   As[m][36]  (bank = g*4+t, conflict-free frag loads)
   Bs[k][136] (bank = t*8+g, conflict-free frag loads)
   EPI: 0=bias, 1=relu(bias), 2=bias+residual
   ===================================================================== */
#define LDA 36
#define LDB 136
template<int EPI>
__global__ void __launch_bounds__(256)
mma_gemm(const float* __restrict__ A, const float* __restrict__ W,
         const float* __restrict__ bias, const float* __restrict__ res,
         float* __restrict__ C, int M, int N, int K)
{
    __shared__ float As[128 * LDA];
    __shared__ float Bs[32 * LDB];

    const int tid = threadIdx.x;
    const int wid = tid >> 5, lane = tid & 31;
    const int g = lane >> 2, t = lane & 3;
    const int wm = wid >> 2, wn = wid & 3;        /* 2 x 4 warps */
    const int row0 = blockIdx.y * 128;
    const int col0 = blockIdx.x * 128;

    float acc[4][4][4];
    #pragma unroll
    for (int mt = 0; mt < 4; mt++)
        #pragma unroll
        for (int nt = 0; nt < 4; nt++)
            #pragma unroll
            for (int i = 0; i < 4; i++) acc[mt][nt][i] = 0.f;

    for (int k0 = 0; k0 < K; k0 += 32) {
        /* stage A: 128 x 32 */
        #pragma unroll
        for (int i = 0; i < 4; i++) {
            int idx = tid + i * 256;
            int m = idx >> 3, kc = (idx & 7) * 4;
            float4 v = *(const float4*)&A[(size_t)(row0 + m) * K + k0 + kc];
            float* d = &As[m * LDA + kc];
            d[0] = to_tf32(v.x); d[1] = to_tf32(v.y);
            d[2] = to_tf32(v.z); d[3] = to_tf32(v.w);
        }
        /* stage B: 32 x 128 */
        #pragma unroll
        for (int i = 0; i < 4; i++) {
            int idx = tid + i * 256;
            int kr = idx >> 5, nc = (idx & 31) * 4;
            float4 v = *(const float4*)&W[(size_t)(k0 + kr) * N + col0 + nc];
            float* d = &Bs[kr * LDB + nc];
            d[0] = to_tf32(v.x); d[1] = to_tf32(v.y);
            d[2] = to_tf32(v.z); d[3] = to_tf32(v.w);
        }
        __syncthreads();

        #pragma unroll
        for (int kk = 0; kk < 32; kk += 8) {
            uint32_t af[4][4], bf[4][2];
            #pragma unroll
            for (int mt = 0; mt < 4; mt++) {
                int mb = wm * 64 + mt * 16 + g;
                af[mt][0] = fu(As[mb * LDA + kk + t]);
                af[mt][1] = fu(As[(mb + 8) * LDA + kk + t]);
                af[mt][2] = fu(As[mb * LDA + kk + t + 4]);
                af[mt][3] = fu(As[(mb + 8) * LDA + kk + t + 4]);
            }
            #pragma unroll
            for (int nt = 0; nt < 4; nt++) {
                int nb = wn * 32 + nt * 8 + g;
                bf[nt][0] = fu(Bs[(kk + t) * LDB + nb]);
                bf[nt][1] = fu(Bs[(kk + t + 4) * LDB + nb]);
            }
            #pragma unroll
            for (int mt = 0; mt < 4; mt++)
                #pragma unroll
                for (int nt = 0; nt < 4; nt++)
                    mma_tf32(acc[mt][nt], af[mt][0], af[mt][1], af[mt][2], af[mt][3],
                             bf[nt][0], bf[nt][1]);
        }
        __syncthreads();
    }

    /* epilogue */
    #pragma unroll
    for (int mt = 0; mt < 4; mt++) {
        #pragma unroll
        for (int half = 0; half < 2; half++) {
            const int r = row0 + wm * 64 + mt * 16 + g + half * 8;
            #pragma unroll
            for (int nt = 0; nt < 4; nt++) {
                const int c = col0 + wn * 32 + nt * 8 + 2 * t;
                float v0 = acc[mt][nt][half * 2 + 0];
                float v1 = acc[mt][nt][half * 2 + 1];
                float2 bv = *(const float2*)&bias[c];
                v0 += bv.x; v1 += bv.y;
                if (EPI == 1) { v0 = fmaxf(v0, 0.f); v1 = fmaxf(v1, 0.f); }
                if (EPI == 2) {
                    float2 rv = *(const float2*)&res[(size_t)r * N + c];
                    v0 += rv.x; v1 += rv.y;
                }
                float2 o; o.x = v0; o.y = v1;
                *(float2*)&C[(size_t)r * N + c] = o;
            }
        }
    }
}

/* =====================================================================
   scores: S[b,h,q,k] = (Q.K^T)/8, masked.  CTA 128q x 128k, Kdim=64.
   Qs[m][36]; Ks[n][36] (K rows are the mma "col" operand).
   ===================================================================== */
__global__ void __launch_bounds__(256)
scores_mma(const float* __restrict__ Q, const float* __restrict__ Kmat,
           const int* __restrict__ mask, float* __restrict__ sc)
{
    __shared__ float Qs[128 * LDA];
    __shared__ float Ks[128 * LDA];

    const int tid = threadIdx.x;
    const int wid = tid >> 5, lane = tid & 31;
    const int g = lane >> 2, t = lane & 3;
    const int wm = wid >> 2, wn = wid & 3;
    const int bh = blockIdx.z;
    const int b = bh >> 4, h = bh & 15;
    const int q0 = blockIdx.y * 128, kb0 = blockIdx.x * 128;

    float acc[4][4][4];
    #pragma unroll
    for (int mt = 0; mt < 4; mt++)
        #pragma unroll
        for (int nt = 0; nt < 4; nt++)
            #pragma unroll
            for (int i = 0; i < 4; i++) acc[mt][nt][i] = 0.f;

    for (int kc0 = 0; kc0 < HDIM; kc0 += 32) {
        #pragma unroll
        for (int i = 0; i < 4; i++) {
            int idx = tid + i * 256;
            int m = idx >> 3, kc = (idx & 7) * 4;
            float4 v = *(const float4*)&Q[((size_t)(b * SS + q0 + m)) * DD + h * HDIM + kc0 + kc];
            float* d = &Qs[m * LDA + kc];
            d[0] = to_tf32(v.x); d[1] = to_tf32(v.y);
            d[2] = to_tf32(v.z); d[3] = to_tf32(v.w);
            float4 w = *(const float4*)&Kmat[((size_t)(b * SS + kb0 + m)) * DD + h * HDIM + kc0 + kc];
            float* e = &Ks[m * LDA + kc];
            e[0] = to_tf32(w.x); e[1] = to_tf32(w.y);
            e[2] = to_tf32(w.z); e[3] = to_tf32(w.w);
        }
        __syncthreads();

        #pragma unroll
        for (int kk = 0; kk < 32; kk += 8) {
            uint32_t af[4][4], bf[4][2];
            #pragma unroll
            for (int mt = 0; mt < 4; mt++) {
                int mb = wm * 64 + mt * 16 + g;
                af[mt][0] = fu(Qs[mb * LDA + kk + t]);
                af[mt][1] = fu(Qs[(mb + 8) * LDA + kk + t]);
                af[mt][2] = fu(Qs[mb * LDA + kk + t + 4]);
                af[mt][3] = fu(Qs[(mb + 8) * LDA + kk + t + 4]);
            }
            #pragma unroll
            for (int nt = 0; nt < 4; nt++) {
                int nb = wn * 32 + nt * 8 + g;
                bf[nt][0] = fu(Ks[nb * LDA + kk + t]);
                bf[nt][1] = fu(Ks[nb * LDA + kk + t + 4]);
            }
            #pragma unroll
            for (int mt = 0; mt < 4; mt++)
                #pragma unroll
                for (int nt = 0; nt < 4; nt++)
                    mma_tf32(acc[mt][nt], af[mt][0], af[mt][1], af[mt][2], af[mt][3],
                             bf[nt][0], bf[nt][1]);
        }
        __syncthreads();
    }

    #pragma unroll
    for (int mt = 0; mt < 4; mt++) {
        #pragma unroll
        for (int half = 0; half < 2; half++) {
            const int q = q0 + wm * 64 + mt * 16 + g + half * 8;
            #pragma unroll
            for (int nt = 0; nt < 4; nt++) {
                const int c = kb0 + wn * 32 + nt * 8 + 2 * t;
                size_t off = ((size_t)bh * SS + q) * SS + c;
                int2 mv = *(const int2*)&mask[off];
                float v0 = acc[mt][nt][half * 2 + 0] * 0.125f;
                float v1 = acc[mt][nt][half * 2 + 1] * 0.125f;
                if (mv.x != 0) v0 = -F_INF;
                if (mv.y != 0) v1 = -F_INF;
                float2 o; o.x = v0; o.y = v1;
                *(float2*)&sc[off] = o;
            }
        }
    }
}

/* =====================================================================
   ctx: ctx[b,q,h,:] = attn[b,h,q,:] @ V[b,:,h,:]
   CTA 128q x 64hd per (b,h). 8 warps 4x2, warp tile 32x32. K step 32.
   attn in As[m][36]; V transposed into Vs[hd][36].
   ===================================================================== */
__global__ void __launch_bounds__(256)
ctx_mma(const float* __restrict__ attn, const float* __restrict__ V,
        float* __restrict__ ctx)
{
    __shared__ float As[128 * LDA];
    __shared__ float Vs[64 * LDA];

    const int tid = threadIdx.x;
    const int wid = tid >> 5, lane = tid & 31;
    const int g = lane >> 2, t = lane & 3;
    const int wm = wid >> 1, wn = wid & 1;        /* 4 x 2 warps */
    const int bh = blockIdx.y;
    const int b = bh >> 4, h = bh & 15;
    const int q0 = blockIdx.x * 128;

    float acc[2][4][4];
    #pragma unroll
    for (int mt = 0; mt < 2; mt++)
        #pragma unroll
        for (int nt = 0; nt < 4; nt++)
            #pragma unroll
            for (int i = 0; i < 4; i++) acc[mt][nt][i] = 0.f;

    for (int k0 = 0; k0 < SS; k0 += 32) {
        #pragma unroll
        for (int i = 0; i < 4; i++) {
            int idx = tid + i * 256;
            int m = idx >> 3, kc = (idx & 7) * 4;
            float4 v = *(const float4*)&attn[((size_t)bh * SS + q0 + m) * SS + k0 + kc];
            float* d = &As[m * LDA + kc];
            d[0] = to_tf32(v.x); d[1] = to_tf32(v.y);
            d[2] = to_tf32(v.z); d[3] = to_tf32(v.w);
        }
        #pragma unroll
        for (int i = 0; i < 2; i++) {
            int idx = tid + i * 256;
            int kr = idx >> 4, cc = (idx & 15) * 4;
            float4 v = *(const float4*)&V[((size_t)(b * SS + k0 + kr)) * DD + h * HDIM + cc];
            Vs[(cc + 0) * LDA + kr] = to_tf32(v.x);
            Vs[(cc + 1) * LDA + kr] = to_tf32(v.y);
            Vs[(cc + 2) * LDA + kr] = to_tf32(v.z);
            Vs[(cc + 3) * LDA + kr] = to_tf32(v.w);
        }
        __syncthreads();

        #pragma unroll
        for (int kk = 0; kk < 32; kk += 8) {
            uint32_t af[2][4], bf[4][2];
            #pragma unroll
            for (int mt = 0; mt < 2; mt++) {
                int mb = wm * 32 + mt * 16 + g;
                af[mt][0] = fu(As[mb * LDA + kk + t]);
                af[mt][1] = fu(As[(mb + 8) * LDA + kk + t]);
                af[mt][2] = fu(As[mb * LDA + kk + t + 4]);
                af[mt][3] = fu(As[(mb + 8) * LDA + kk + t + 4]);
            }
            #pragma unroll
            for (int nt = 0; nt < 4; nt++) {
                int nb = wn * 32 + nt * 8 + g;
                bf[nt][0] = fu(Vs[nb * LDA + kk + t]);
                bf[nt][1] = fu(Vs[nb * LDA + kk + t + 4]);
            }
            #pragma unroll
            for (int mt = 0; mt < 2; mt++)
                #pragma unroll
                for (int nt = 0; nt < 4; nt++)
                    mma_tf32(acc[mt][nt], af[mt][0], af[mt][1], af[mt][2], af[mt][3],
                             bf[nt][0], bf[nt][1]);
        }
        __syncthreads();
    }

    #pragma unroll
    for (int mt = 0; mt < 2; mt++) {
        #pragma unroll
        for (int half = 0; half < 2; half++) {
            const int q = q0 + wm * 32 + mt * 16 + g + half * 8;
            #pragma unroll
            for (int nt = 0; nt < 4; nt++) {
                const int c = wn * 32 + nt * 8 + 2 * t;
                float2 o;
                o.x = acc[mt][nt][half * 2 + 0];
                o.y = acc[mt][nt][half * 2 + 1];
                *(float2*)&ctx[((size_t)(b * SS + q)) * DD + h * HDIM + c] = o;
            }
        }
    }
}

/* ---------------- softmax over last dim, in place ---------------- */
__global__ void __launch_bounds__(256)
softmax_kernel(float* __restrict__ sc)
{
    __shared__ float red[8];
    const size_t base = (size_t)blockIdx.x * SS;
    const int tid = threadIdx.x;
    float v[4];
    #pragma unroll
    for (int i = 0; i < 4; i++) v[i] = sc[base + tid + i * 256];

    float m = fmaxf(fmaxf(v[0], v[1]), fmaxf(v[2], v[3]));
    m = blockMax(m, red);

    float p[4], s = 0.f;
    #pragma unroll
    for (int i = 0; i < 4; i++) { p[i] = __expf(v[i] - m); s += p[i]; }
    s = blockSum(s, red);
    const float inv = 1.f / s;
    #pragma unroll
    for (int i = 0; i < 4; i++) sc[base + tid + i * 256] = p[i] * inv;
}

/* ---------------- LayerNorm over D ---------------- */
__global__ void __launch_bounds__(256)
ln_kernel(const float* __restrict__ in, const float* __restrict__ g,
          const float* __restrict__ beta, float* __restrict__ out)
{
    __shared__ float red[8];
    const size_t base = (size_t)blockIdx.x * DD;
    const int tid = threadIdx.x;
    float v[4];
    #pragma unroll
    for (int i = 0; i < 4; i++) v[i] = in[base + tid + i * 256];

    float s = v[0] + v[1] + v[2] + v[3];
    const float mu = blockSum(s, red) * (1.f / DD);

    float sq = 0.f;
    #pragma unroll
    for (int i = 0; i < 4; i++) { v[i] -= mu; sq += v[i] * v[i]; }
    const float var = blockSum(sq, red) * (1.f / DD);
    const float r = rsqrtf(var + LN_EPS);

    #pragma unroll
    for (int i = 0; i < 4; i++) {
        int c = tid + i * 256;
        out[base + c] = v[i] * r * g[c] + beta[c];
    }
}

/* ---------------- launch ---------------- */
extern "C" void kernel_launch(void* const* d_in, const int* in_sizes, int n_in,
                              void* d_out, int out_size)
{
    const float* x    = (const float*)d_in[0];
    const float* y    = (const float*)d_in[1];
    const int* mask   = (const int*)d_in[2];
    const float* Wq = (const float*)d_in[3];
    const float* bq = (const float*)d_in[4];
    const float* Wk = (const float*)d_in[5];
    const float* bk = (const float*)d_in[6];
    const float* Wv = (const float*)d_in[7];
    const float* bv = (const float*)d_in[8];
    const float* Wo = (const float*)d_in[9];
    const float* bo = (const float*)d_in[10];
    const float* W1 = (const float*)d_in[11];
    const float* b1 = (const float*)d_in[12];
    const float* W2 = (const float*)d_in[13];
    const float* b2 = (const float*)d_in[14];
    const float* g1 = (const float*)d_in[15];
    const float* be1 = (const float*)d_in[16];
    const float* g2 = (const float*)d_in[17];
    const float* be2 = (const float*)d_in[18];
    float* out = (float*)d_out;

    float* pool = nullptr;
    cudaGetSymbolAddress((void**)&pool, g_pool);
    float* q   = pool + OFF_Q;
    float* k   = pool + OFF_K;
    float* v   = pool + OFF_V;
    float* ctx = pool + OFF_CTX;
    float* x1  = pool + OFF_X1;
    float* tmp = pool + OFF_TMP;
    float* h   = pool + OFF_H;
    float* sc  = pool + OFF_SC;

    dim3 gProj(DD / 128, MROWS / 128);      /* 8 x 32 */
    dim3 gFF1(FFD / 128, MROWS / 128);      /* 32 x 32 */

    /* QKV projections */
    mma_gemm<0><<<gProj, 256>>>(x, Wq, bq, nullptr, q, MROWS, DD, DD);
    mma_gemm<0><<<gProj, 256>>>(y, Wk, bk, nullptr, k, MROWS, DD, DD);
    mma_gemm<0><<<gProj, 256>>>(y, Wv, bv, nullptr, v, MROWS, DD, DD);

    /* attention */
    scores_mma<<<dim3(SS / 128, SS / 128, BB * HH), 256>>>(q, k, mask, sc);
    softmax_kernel<<<BB * HH * SS, 256>>>(sc);
    ctx_mma<<<dim3(SS / 128, BB * HH), 256>>>(sc, v, ctx);

    /* output proj + residual, LN1 */
    mma_gemm<2><<<gProj, 256>>>(ctx, Wo, bo, x, tmp, MROWS, DD, DD);
    ln_kernel<<<MROWS, 256>>>(tmp, g1, be1, x1);

    /* FFN */
    mma_gemm<1><<<gFF1, 256>>>(x1, W1, b1, nullptr, h, MROWS, FFD, DD);
    mma_gemm<2><<<gProj, 256>>>(h, W2, b2, x1, tmp, MROWS, DD, FFD);
    ln_kernel<<<MROWS, 256>>>(tmp, g2, be2, out);
}

// round 5
// speedup vs baseline: 3.5790x; 1.3097x over previous
#include <cuda_runtime.h>
#include <math.h>
#include <stdint.h>

#define BB 4
#define SS 1024
#define DD 1024
#define HH 16
#define HDIM 64
#define MROWS (BB*SS)   /* 4096 */
#define FFD (4*DD)      /* 4096 */
#define LN_EPS 1e-5f

/* ---------------- scratch pool ---------------- */
#define OFF_Q   (0ul)
#define OFF_K   (4ul<<20)
#define OFF_V   (8ul<<20)
#define OFF_CTX (12ul<<20)
#define OFF_X1  (16ul<<20)
#define OFF_TMP (20ul<<20)
#define OFF_H   (24ul<<20)
#define POOL_FLOATS (40ul<<20)
__device__ __align__(256) float g_pool[POOL_FLOATS];

/* ---------------- helpers ---------------- */
__device__ __forceinline__ float to_tf32(float x) {
    uint32_t r;
    asm("cvt.rna.tf32.f32 %0, %1;" : "=r"(r) : "f"(x));
    return __uint_as_float(r);
}
__device__ __forceinline__ void mma_tf32(float c[4],
                                         uint32_t a0, uint32_t a1, uint32_t a2, uint32_t a3,
                                         uint32_t b0, uint32_t b1) {
    asm volatile(
        "mma.sync.aligned.m16n8k8.row.col.f32.tf32.tf32.f32 "
        "{%0,%1,%2,%3}, {%4,%5,%6,%7}, {%8,%9}, {%0,%1,%2,%3};"
        : "+f"(c[0]), "+f"(c[1]), "+f"(c[2]), "+f"(c[3])
        : "r"(a0), "r"(a1), "r"(a2), "r"(a3), "r"(b0), "r"(b1));
}
__device__ __forceinline__ uint32_t fu(float x) { return __float_as_uint(x); }

__device__ __forceinline__ void cp_async16(void* dst, const void* src) {
    uint32_t s = (uint32_t)__cvta_generic_to_shared(dst);
    asm volatile("cp.async.cg.shared.global [%0], [%1], 16;\n" :: "r"(s), "l"(src));
}
#define CP_COMMIT() asm volatile("cp.async.commit_group;\n" ::: "memory")
#define CP_WAIT0()  asm volatile("cp.async.wait_group 0;\n" ::: "memory")

__device__ __forceinline__ float warpSum(float v) {
    #pragma unroll
    for (int o = 16; o; o >>= 1) v += __shfl_xor_sync(0xffffffffu, v, o);
    return v;
}
__device__ __forceinline__ float blockSum(float v, float* red) {
    int lane = threadIdx.x & 31, w = threadIdx.x >> 5;
    v = warpSum(v);
    __syncthreads();
    if (lane == 0) red[w] = v;
    __syncthreads();
    float r = (lane < 8) ? red[lane] : 0.f;
    return warpSum(r);
}

/* =====================================================================
   Dense GEMM, cp.async double-buffered tf32 mma.
   CTA 128x128, 256 thr, warp 64x32, K step 32.
   As[m][36] (A-frag conflict-free), Bs[k][136] (B-frag conflict-free).
   EPI: 0=bias, 1=relu(bias), 2=bias+residual
   ===================================================================== */
#define LDA 36
#define LDB 136
#define AS_TILE (128*LDA)
#define BS_TILE (32*LDB)
#define GEMM_SMEM ((2*AS_TILE + 2*BS_TILE)*4)

template<int EPI>
__global__ void __launch_bounds__(256)
mma_gemm(const float* __restrict__ A, const float* __restrict__ W,
         const float* __restrict__ bias, const float* __restrict__ res,
         float* __restrict__ C, int M, int N, int K)
{
    extern __shared__ float sm[];
    float* As = sm;
    float* Bs = sm + 2*AS_TILE;

    const int tid = threadIdx.x;
    const int wid = tid >> 5, lane = tid & 31;
    const int g = lane >> 2, t = lane & 3;
    const int wm = wid >> 2, wn = wid & 3;
    const int row0 = blockIdx.y * 128;
    const int col0 = blockIdx.x * 128;

    float acc[4][4][4];
    #pragma unroll
    for (int mt = 0; mt < 4; mt++)
        #pragma unroll
        for (int nt = 0; nt < 4; nt++)
            #pragma unroll
            for (int i = 0; i < 4; i++) acc[mt][nt][i] = 0.f;

    /* prologue: stage tile 0 into buf 0 */
    #pragma unroll
    for (int i = 0; i < 4; i++) {
        int idx = tid + i * 256;
        int m = idx >> 3, kc = (idx & 7) * 4;
        cp_async16(&As[m * LDA + kc], &A[(size_t)(row0 + m) * K + kc]);
    }
    #pragma unroll
    for (int i = 0; i < 4; i++) {
        int idx = tid + i * 256;
        int kr = idx >> 5, nc = (idx & 31) * 4;
        cp_async16(&Bs[kr * LDB + nc], &W[(size_t)kr * N + col0 + nc]);
    }
    CP_COMMIT();

    const int nit = K >> 5;
    for (int it = 0; it < nit; it++) {
        const int buf = it & 1;
        const float* Ab = As + buf * AS_TILE;
        const float* Bb = Bs + buf * BS_TILE;
        CP_WAIT0();
        __syncthreads();

        if (it + 1 < nit) {
            const int k0 = (it + 1) << 5;
            float* An = As + (buf ^ 1) * AS_TILE;
            float* Bn = Bs + (buf ^ 1) * BS_TILE;
            #pragma unroll
            for (int i = 0; i < 4; i++) {
                int idx = tid + i * 256;
                int m = idx >> 3, kc = (idx & 7) * 4;
                cp_async16(&An[m * LDA + kc], &A[(size_t)(row0 + m) * K + k0 + kc]);
            }
            #pragma unroll
            for (int i = 0; i < 4; i++) {
                int idx = tid + i * 256;
                int kr = idx >> 5, nc = (idx & 31) * 4;
                cp_async16(&Bn[kr * LDB + nc], &W[(size_t)(k0 + kr) * N + col0 + nc]);
            }
            CP_COMMIT();
        }

        #pragma unroll
        for (int kk = 0; kk < 32; kk += 8) {
            uint32_t af[4][4], bf[4][2];
            #pragma unroll
            for (int mt = 0; mt < 4; mt++) {
                int mb = wm * 64 + mt * 16 + g;
                af[mt][0] = fu(Ab[mb * LDA + kk + t]);
                af[mt][1] = fu(Ab[(mb + 8) * LDA + kk + t]);
                af[mt][2] = fu(Ab[mb * LDA + kk + t + 4]);
                af[mt][3] = fu(Ab[(mb + 8) * LDA + kk + t + 4]);
            }
            #pragma unroll
            for (int nt = 0; nt < 4; nt++) {
                int nb = wn * 32 + nt * 8 + g;
                bf[nt][0] = fu(Bb[(kk + t) * LDB + nb]);
                bf[nt][1] = fu(Bb[(kk + t + 4) * LDB + nb]);
            }
            #pragma unroll
            for (int mt = 0; mt < 4; mt++)
                #pragma unroll
                for (int nt = 0; nt < 4; nt++)
                    mma_tf32(acc[mt][nt], af[mt][0], af[mt][1], af[mt][2], af[mt][3],
                             bf[nt][0], bf[nt][1]);
        }
    }

    #pragma unroll
    for (int mt = 0; mt < 4; mt++) {
        #pragma unroll
        for (int half = 0; half < 2; half++) {
            const int r = row0 + wm * 64 + mt * 16 + g + half * 8;
            #pragma unroll
            for (int nt = 0; nt < 4; nt++) {
                const int c = col0 + wn * 32 + nt * 8 + 2 * t;
                float v0 = acc[mt][nt][half * 2 + 0];
                float v1 = acc[mt][nt][half * 2 + 1];
                float2 bv = *(const float2*)&bias[c];
                v0 += bv.x; v1 += bv.y;
                if (EPI == 1) { v0 = fmaxf(v0, 0.f); v1 = fmaxf(v1, 0.f); }
                if (EPI == 2) {
                    float2 rv = *(const float2*)&res[(size_t)r * N + c];
                    v0 += rv.x; v1 += rv.y;
                }
                float2 o; o.x = v0; o.y = v1;
                *(float2*)&C[(size_t)r * N + c] = o;
            }
        }
    }
}

/* =====================================================================
   Fused attention (no-max softmax): per CTA = (b,h, 128 q rows).
   Loop 16 kv-tiles of 64: QK^T mma -> mask+exp -> P smem -> P.V mma.
   Unnormalized O and row sums accumulate; normalize at end.
   smem: Qs[128][68] Ks[64][68] Vs[64][72] Ps[128][68] rsum[128]
   ===================================================================== */
#define LDQ 68
#define LDV 72
#define FL_SMEM ((128*LDQ + 64*LDQ + 64*LDV + 128*LDQ + 128)*4)

__global__ void __launch_bounds__(256, 2)
flash_attn(const float* __restrict__ Q, const float* __restrict__ Kg,
           const float* __restrict__ Vg, const int* __restrict__ mask,
           float* __restrict__ ctx)
{
    extern __shared__ float sm[];
    float* Qs = sm;                 /* [128][68] */
    float* Ks = Qs + 128 * LDQ;     /* [64][68]  */
    float* Vs = Ks + 64 * LDQ;      /* [64][72]  k-major */
    float* Ps = Vs + 64 * LDV;      /* [128][68] */
    float* rsum = Ps + 128 * LDQ;   /* [128]     */

    const int tid = threadIdx.x;
    const int wid = tid >> 5, lane = tid & 31;
    const int g = lane >> 2, t = lane & 3;
    const int wm = wid >> 2, wn = wid & 3;
    const int q0 = blockIdx.x * 128;
    const int bh = blockIdx.y;
    const int b = bh >> 4, h = bh & 15;

    if (tid < 128) rsum[tid] = 0.f;

    /* load Q tile once */
    const float* Qbase = Q + ((size_t)(b * SS + q0)) * DD + h * HDIM;
    #pragma unroll
    for (int i = 0; i < 8; i++) {
        int idx = tid + i * 256;
        int m = idx >> 4, c = (idx & 15) * 4;
        cp_async16(&Qs[m * LDQ + c], Qbase + (size_t)m * DD + c);
    }
    CP_COMMIT();

    float acc_o[4][2][4];
    #pragma unroll
    for (int mt = 0; mt < 4; mt++)
        #pragma unroll
        for (int nt = 0; nt < 2; nt++)
            #pragma unroll
            for (int i = 0; i < 4; i++) acc_o[mt][nt][i] = 0.f;
    float rs[8];
    #pragma unroll
    for (int i = 0; i < 8; i++) rs[i] = 0.f;

    const float* Kb0 = Kg + ((size_t)b * SS) * DD + h * HDIM;
    const float* Vb0 = Vg + ((size_t)b * SS) * DD + h * HDIM;

    for (int kt = 0; kt < 16; kt++) {
        const float* Kt = Kb0 + (size_t)(kt * 64) * DD;
        const float* Vt = Vb0 + (size_t)(kt * 64) * DD;
        #pragma unroll
        for (int i = 0; i < 4; i++) {
            int idx = tid + i * 256;
            int r = idx >> 4, c = (idx & 15) * 4;
            cp_async16(&Ks[r * LDQ + c], Kt + (size_t)r * DD + c);
            cp_async16(&Vs[r * LDV + c], Vt + (size_t)r * DD + c);
        }
        CP_COMMIT();
        CP_WAIT0();
        __syncthreads();

        /* S = Q(128x64) . K^T -> 128x64, warp tile 64x16 */
        float acc_s[4][2][4];
        #pragma unroll
        for (int mt = 0; mt < 4; mt++)
            #pragma unroll
            for (int nt = 0; nt < 2; nt++)
                #pragma unroll
                for (int i = 0; i < 4; i++) acc_s[mt][nt][i] = 0.f;

        #pragma unroll
        for (int kk = 0; kk < 64; kk += 8) {
            uint32_t af[4][4], bf[2][2];
            #pragma unroll
            for (int mt = 0; mt < 4; mt++) {
                int mb = wm * 64 + mt * 16 + g;
                af[mt][0] = fu(Qs[mb * LDQ + kk + t]);
                af[mt][1] = fu(Qs[(mb + 8) * LDQ + kk + t]);
                af[mt][2] = fu(Qs[mb * LDQ + kk + t + 4]);
                af[mt][3] = fu(Qs[(mb + 8) * LDQ + kk + t + 4]);
            }
            #pragma unroll
            for (int nt = 0; nt < 2; nt++) {
                int nb = wn * 16 + nt * 8 + g;
                bf[nt][0] = fu(Ks[nb * LDQ + kk + t]);
                bf[nt][1] = fu(Ks[nb * LDQ + kk + t + 4]);
            }
            #pragma unroll
            for (int mt = 0; mt < 4; mt++)
                #pragma unroll
                for (int nt = 0; nt < 2; nt++)
                    mma_tf32(acc_s[mt][nt], af[mt][0], af[mt][1], af[mt][2], af[mt][3],
                             bf[nt][0], bf[nt][1]);
        }

        /* mask + exp + store P + row-sum partials */
        #pragma unroll
        for (int mt = 0; mt < 4; mt++) {
            #pragma unroll
            for (int half = 0; half < 2; half++) {
                const int row = wm * 64 + mt * 16 + g + half * 8;
                const size_t moff = ((size_t)bh * SS + q0 + row) * SS + kt * 64;
                #pragma unroll
                for (int nt = 0; nt < 2; nt++) {
                    const int col = wn * 16 + nt * 8 + 2 * t;
                    int2 mv = *(const int2*)&mask[moff + col];
                    float s0 = acc_s[mt][nt][half * 2 + 0] * 0.125f;
                    float s1 = acc_s[mt][nt][half * 2 + 1] * 0.125f;
                    float p0 = mv.x ? 0.f : __expf(s0);
                    float p1 = mv.y ? 0.f : __expf(s1);
                    rs[mt * 2 + half] += p0 + p1;
                    float2 pv; pv.x = to_tf32(p0); pv.y = to_tf32(p1);
                    *(float2*)&Ps[row * LDQ + col] = pv;
                }
            }
        }
        __syncthreads();

        /* O += P(128x64) . V(64x64) */
        #pragma unroll
        for (int kk = 0; kk < 64; kk += 8) {
            uint32_t af[4][4], bf[2][2];
            #pragma unroll
            for (int mt = 0; mt < 4; mt++) {
                int mb = wm * 64 + mt * 16 + g;
                af[mt][0] = fu(Ps[mb * LDQ + kk + t]);
                af[mt][1] = fu(Ps[(mb + 8) * LDQ + kk + t]);
                af[mt][2] = fu(Ps[mb * LDQ + kk + t + 4]);
                af[mt][3] = fu(Ps[(mb + 8) * LDQ + kk + t + 4]);
            }
            #pragma unroll
            for (int nt = 0; nt < 2; nt++) {
                int nb = wn * 16 + nt * 8 + g;
                bf[nt][0] = fu(Vs[(kk + t) * LDV + nb]);
                bf[nt][1] = fu(Vs[(kk + t + 4) * LDV + nb]);
            }
            #pragma unroll
            for (int mt = 0; mt < 4; mt++)
                #pragma unroll
                for (int nt = 0; nt < 2; nt++)
                    mma_tf32(acc_o[mt][nt], af[mt][0], af[mt][1], af[mt][2], af[mt][3],
                             bf[nt][0], bf[nt][1]);
        }
        __syncthreads();
    }

    /* reduce row sums across (t, wn) */
    #pragma unroll
    for (int mt = 0; mt < 4; mt++)
        #pragma unroll
        for (int half = 0; half < 2; half++) {
            const int row = wm * 64 + mt * 16 + g + half * 8;
            atomicAdd(&rsum[row], rs[mt * 2 + half]);
        }
    __syncthreads();

    /* normalize + write ctx[b, q, h*64 + hd] */
    #pragma unroll
    for (int mt = 0; mt < 4; mt++) {
        #pragma unroll
        for (int half = 0; half < 2; half++) {
            const int row = wm * 64 + mt * 16 + g + half * 8;
            const float inv = 1.f / rsum[row];
            #pragma unroll
            for (int nt = 0; nt < 2; nt++) {
                const int col = wn * 16 + nt * 8 + 2 * t;
                float2 o;
                o.x = acc_o[mt][nt][half * 2 + 0] * inv;
                o.y = acc_o[mt][nt][half * 2 + 1] * inv;
                *(float2*)&ctx[((size_t)(b * SS + q0 + row)) * DD + h * HDIM + col] = o;
            }
        }
    }
}

/* ---------------- LayerNorm over D ---------------- */
__global__ void __launch_bounds__(256)
ln_kernel(const float* __restrict__ in, const float* __restrict__ g,
          const float* __restrict__ beta, float* __restrict__ out)
{
    __shared__ float red[8];
    const size_t base = (size_t)blockIdx.x * DD;
    const int tid = threadIdx.x;
    float v[4];
    #pragma unroll
    for (int i = 0; i < 4; i++) v[i] = in[base + tid + i * 256];

    float s = v[0] + v[1] + v[2] + v[3];
    const float mu = blockSum(s, red) * (1.f / DD);

    float sq = 0.f;
    #pragma unroll
    for (int i = 0; i < 4; i++) { v[i] -= mu; sq += v[i] * v[i]; }
    const float var = blockSum(sq, red) * (1.f / DD);
    const float r = rsqrtf(var + LN_EPS);

    #pragma unroll
    for (int i = 0; i < 4; i++) {
        int c = tid + i * 256;
        out[base + c] = v[i] * r * g[c] + beta[c];
    }
}

/* ---------------- launch ---------------- */
extern "C" void kernel_launch(void* const* d_in, const int* in_sizes, int n_in,
                              void* d_out, int out_size)
{
    const float* x    = (const float*)d_in[0];
    const float* y    = (const float*)d_in[1];
    const int* mask   = (const int*)d_in[2];
    const float* Wq = (const float*)d_in[3];
    const float* bq = (const float*)d_in[4];
    const float* Wk = (const float*)d_in[5];
    const float* bk = (const float*)d_in[6];
    const float* Wv = (const float*)d_in[7];
    const float* bv = (const float*)d_in[8];
    const float* Wo = (const float*)d_in[9];
    const float* bo = (const float*)d_in[10];
    const float* W1 = (const float*)d_in[11];
    const float* b1 = (const float*)d_in[12];
    const float* W2 = (const float*)d_in[13];
    const float* b2 = (const float*)d_in[14];
    const float* g1 = (const float*)d_in[15];
    const float* be1 = (const float*)d_in[16];
    const float* g2 = (const float*)d_in[17];
    const float* be2 = (const float*)d_in[18];
    float* out = (float*)d_out;

    cudaFuncSetAttribute(mma_gemm<0>, cudaFuncAttributeMaxDynamicSharedMemorySize, GEMM_SMEM);
    cudaFuncSetAttribute(mma_gemm<1>, cudaFuncAttributeMaxDynamicSharedMemorySize, GEMM_SMEM);
    cudaFuncSetAttribute(mma_gemm<2>, cudaFuncAttributeMaxDynamicSharedMemorySize, GEMM_SMEM);
    cudaFuncSetAttribute(flash_attn, cudaFuncAttributeMaxDynamicSharedMemorySize, FL_SMEM);

    float* pool = nullptr;
    cudaGetSymbolAddress((void**)&pool, g_pool);
    float* q   = pool + OFF_Q;
    float* k   = pool + OFF_K;
    float* v   = pool + OFF_V;
    float* ctx = pool + OFF_CTX;
    float* x1  = pool + OFF_X1;
    float* tmp = pool + OFF_TMP;
    float* h   = pool + OFF_H;

    dim3 gProj(DD / 128, MROWS / 128);      /* 8 x 32 */
    dim3 gFF1(FFD / 128, MROWS / 128);      /* 32 x 32 */

    /* QKV projections */
    mma_gemm<0><<<gProj, 256, GEMM_SMEM>>>(x, Wq, bq, nullptr, q, MROWS, DD, DD);
    mma_gemm<0><<<gProj, 256, GEMM_SMEM>>>(y, Wk, bk, nullptr, k, MROWS, DD, DD);
    mma_gemm<0><<<gProj, 256, GEMM_SMEM>>>(y, Wv, bv, nullptr, v, MROWS, DD, DD);

    /* fused attention */
    flash_attn<<<dim3(SS / 128, BB * HH), 256, FL_SMEM>>>(q, k, v, mask, ctx);

    /* output proj + residual, LN1 */
    mma_gemm<2><<<gProj, 256, GEMM_SMEM>>>(ctx, Wo, bo, x, tmp, MROWS, DD, DD);
    ln_kernel<<<MROWS, 256>>>(tmp, g1, be1, x1);

    /* FFN */
    mma_gemm<1><<<gFF1, 256, GEMM_SMEM>>>(x1, W1, b1, nullptr, h, MROWS, FFD, DD);
    mma_gemm<2><<<gProj, 256, GEMM_SMEM>>>(h, W2, b2, x1, tmp, MROWS, DD, FFD);
    ln_kernel<<<MROWS, 256>>>(tmp, g2, be2, out);
}